// round 3
// baseline (speedup 1.0000x reference)
#include <cuda_runtime.h>
#include <cstdint>

// Problem constants (sizes also read from in_sizes at launch)
#define CN 50000
#define CE 600000
#define CEP (CE + CN)

// ---------------- device scratch (static: no allocations allowed) -----------
__device__ __align__(16) float    g_h   [(size_t)CN * 128];
__device__ __align__(16) float    g_xl  [(size_t)CN * 128];
__device__ __align__(16) float    g_xr  [(size_t)CN * 128];
__device__ __align__(16) float    g_agg [(size_t)CN * 128];
__device__ __align__(16) float    g_loop[(size_t)CN * 16];
__device__ __align__(16) float    g_deg [CN];
__device__ __align__(16) float    g_logit[(size_t)CEP * 4];
__device__ __align__(16) unsigned g_mx  [CN * 4];
__device__ __align__(16) float    g_den [CN * 4];
__device__ int g_is64;
__device__ __align__(16) int g_src[CE];
__device__ __align__(16) int g_dst[CE];

// monotonic float<->unsigned encoding for atomicMax on floats
__device__ __forceinline__ unsigned fenc(float f){
    unsigned u = __float_as_uint(f);
    return (u & 0x80000000u) ? ~u : (u | 0x80000000u);
}
__device__ __forceinline__ float fdec(unsigned u){
    return (u & 0x80000000u) ? __uint_as_float(u & 0x7fffffffu) : __uint_as_float(~u);
}

// ---------------- index dtype detection + normalization ---------------------
// If edge_index is int64, the high 32-bit word of every entry is 0 (values < N).
// If int32, the sampled words are random src indices -> virtually never all 0.
__global__ void k_detect(const int* __restrict__ idx){
    __shared__ int s_or;
    if (threadIdx.x == 0) s_or = 0;
    __syncthreads();
    int v = 0;
    for (int i = threadIdx.x; i < 1024; i += blockDim.x) v |= idx[2 * i + 1];
    atomicOr(&s_or, v);
    __syncthreads();
    if (threadIdx.x == 0) g_is64 = (s_or == 0) ? 1 : 0;
}

__global__ void k_convert(const int* __restrict__ idx, int E){
    int e = blockIdx.x * blockDim.x + threadIdx.x;
    if (e >= E) return;
    if (g_is64){
        g_src[e] = idx[2 * e];
        g_dst[e] = idx[2 * (E + e)];
    } else {
        g_src[e] = idx[e];
        g_dst[e] = idx[E + e];
    }
}

// ---------------- pre-pass: degree + self-loop edge_attr (mean) -------------
__global__ void k_zero_pre(int N){
    int i = blockIdx.x * blockDim.x + threadIdx.x;
    if (i < N * 16) g_loop[i] = 0.f;
    if (i < N)      g_deg[i]  = 0.f;
}

__global__ void k_deg(const float* __restrict__ ea, int E){
    int i = blockIdx.x * blockDim.x + threadIdx.x;
    if (i >= E * 16) return;
    int e = i >> 4, j = i & 15;
    int d = g_dst[e];
    atomicAdd(&g_loop[d * 16 + j], ea[i]);
    if (j == 0) atomicAdd(&g_deg[d], 1.f);
}

__global__ void k_loopdiv(int N){
    int i = blockIdx.x * blockDim.x + threadIdx.x;
    if (i >= N * 16) return;
    g_loop[i] /= fmaxf(g_deg[i >> 4], 1.f);
}

// ---------------- GEMM: g_h[M,128] = A[M,128] @ W[128,128] + b --------------
// 16 rows per block, 128 threads; A tile smem-broadcast, 16 FMA per W load.
__global__ void k_gemm128(const float* __restrict__ A, const float* __restrict__ W,
                          const float* __restrict__ b, int M){
    __shared__ float4 sA[512];          // 16 rows x 32 float4
    int row0 = blockIdx.x * 16;
    int t = threadIdx.x;
    const float4* A4 = (const float4*)A;
    for (int i = t; i < 512; i += 128){
        int r = i >> 5, c = i & 31;
        sA[i] = (row0 + r < M) ? A4[(size_t)(row0 + r) * 32 + c] : make_float4(0,0,0,0);
    }
    __syncthreads();
    float acc[16];
    float bv = b[t];
    #pragma unroll
    for (int r = 0; r < 16; r++) acc[r] = bv;
    for (int k4 = 0; k4 < 32; k4++){
        int kb = k4 * 512 + t;
        float w0 = W[kb], w1 = W[kb + 128], w2 = W[kb + 256], w3 = W[kb + 384];
        #pragma unroll
        for (int r = 0; r < 16; r++){
            float4 a = sA[r * 32 + k4];
            acc[r] = fmaf(a.x, w0, acc[r]);
            acc[r] = fmaf(a.y, w1, acc[r]);
            acc[r] = fmaf(a.z, w2, acc[r]);
            acc[r] = fmaf(a.w, w3, acc[r]);
        }
    }
    #pragma unroll
    for (int r = 0; r < 16; r++)
        if (row0 + r < M) g_h[(size_t)(row0 + r) * 128 + t] = acc[r];
}

// Fused: xl = h@Wl+bl, xr = h@Wr+br  (shares the A tile load)
__global__ void k_dualgemm(const float* __restrict__ Wl, const float* __restrict__ bl,
                           const float* __restrict__ Wr, const float* __restrict__ br, int M){
    __shared__ float4 sA[512];
    int row0 = blockIdx.x * 16;
    int t = threadIdx.x;
    const float4* A4 = (const float4*)g_h;
    for (int i = t; i < 512; i += 128){
        int r = i >> 5, c = i & 31;
        sA[i] = (row0 + r < M) ? A4[(size_t)(row0 + r) * 32 + c] : make_float4(0,0,0,0);
    }
    __syncthreads();
    float accL[16], accR[16];
    float bL = bl[t], bR = br[t];
    #pragma unroll
    for (int r = 0; r < 16; r++){ accL[r] = bL; accR[r] = bR; }
    for (int k4 = 0; k4 < 32; k4++){
        int kb = k4 * 512 + t;
        float l0 = Wl[kb], l1 = Wl[kb + 128], l2 = Wl[kb + 256], l3 = Wl[kb + 384];
        float r0 = Wr[kb], r1 = Wr[kb + 128], r2 = Wr[kb + 256], r3 = Wr[kb + 384];
        #pragma unroll
        for (int r = 0; r < 16; r++){
            float4 a = sA[r * 32 + k4];
            accL[r] = fmaf(a.x, l0, accL[r]);
            accL[r] = fmaf(a.y, l1, accL[r]);
            accL[r] = fmaf(a.z, l2, accL[r]);
            accL[r] = fmaf(a.w, l3, accL[r]);
            accR[r] = fmaf(a.x, r0, accR[r]);
            accR[r] = fmaf(a.y, r1, accR[r]);
            accR[r] = fmaf(a.z, r2, accR[r]);
            accR[r] = fmaf(a.w, r3, accR[r]);
        }
    }
    #pragma unroll
    for (int r = 0; r < 16; r++){
        if (row0 + r < M){
            g_xl[(size_t)(row0 + r) * 128 + t] = accL[r];
            g_xr[(size_t)(row0 + r) * 128 + t] = accR[r];
        }
    }
}

// ---------------- per-layer zeroing ----------------------------------------
__global__ void k_zero_layer(int N){
    int i = blockIdx.x * blockDim.x + threadIdx.x;
    if (i < N * 32) ((float4*)g_agg)[i] = make_float4(0,0,0,0);
    if (i < N * 4){ g_mx[i] = 0u; g_den[i] = 0.f; }
}

// ---------------- edge logits + running max (warp per edge, grid-stride) ----
// We[l] (16x128) held in registers per lane (its 4 columns). ee computed on the fly.
__global__ void k_logit(const float* __restrict__ ea, const float* __restrict__ We_l,
                        const float* __restrict__ att_l, int E, int EP){
    int lane = threadIdx.x & 31;
    int w  = (blockIdx.x * blockDim.x + threadIdx.x) >> 5;
    int nw = (gridDim.x * blockDim.x) >> 5;
    float we[4][16], attv[4];
    #pragma unroll
    for (int h = 0; h < 4; h++){
        int col = lane + 32 * h;
        attv[h] = att_l[col];
        #pragma unroll
        for (int j = 0; j < 16; j++) we[h][j] = We_l[j * 128 + col];
    }
    for (int e = w; e < EP; e += nw){
        int s, d; const float4* ap;
        if (e < E){ s = g_src[e]; d = g_dst[e]; ap = (const float4*)(ea + (size_t)e * 16); }
        else      { s = e - E; d = s; ap = (const float4*)(g_loop + (size_t)(e - E) * 16); }
        float4 q0 = ap[0], q1 = ap[1], q2 = ap[2], q3 = ap[3];
        float av[16] = {q0.x,q0.y,q0.z,q0.w, q1.x,q1.y,q1.z,q1.w,
                        q2.x,q2.y,q2.z,q2.w, q3.x,q3.y,q3.z,q3.w};
        const float* xls = g_xl + (size_t)s * 128;
        const float* xrd = g_xr + (size_t)d * 128;
        float lg[4];
        #pragma unroll
        for (int h = 0; h < 4; h++){
            int col = lane + 32 * h;
            float eev = 0.f;
            #pragma unroll
            for (int j = 0; j < 16; j++) eev = fmaf(av[j], we[h][j], eev);
            float m = xls[col] + xrd[col] + eev;
            m = m > 0.f ? m : 0.2f * m;          // LeakyReLU(0.2)
            lg[h] = m * attv[h];
        }
        #pragma unroll
        for (int off = 16; off; off >>= 1){
            lg[0] += __shfl_xor_sync(~0u, lg[0], off);
            lg[1] += __shfl_xor_sync(~0u, lg[1], off);
            lg[2] += __shfl_xor_sync(~0u, lg[2], off);
            lg[3] += __shfl_xor_sync(~0u, lg[3], off);
        }
        if (lane == 0){
            ((float4*)g_logit)[e] = make_float4(lg[0], lg[1], lg[2], lg[3]);
            atomicMax(&g_mx[d * 4 + 0], fenc(lg[0]));
            atomicMax(&g_mx[d * 4 + 1], fenc(lg[1]));
            atomicMax(&g_mx[d * 4 + 2], fenc(lg[2]));
            atomicMax(&g_mx[d * 4 + 3], fenc(lg[3]));
        }
    }
}

// ---------------- exp(logit - max) + denominator ----------------------------
__global__ void k_exp(int E, int EP){
    int i = blockIdx.x * blockDim.x + threadIdx.x;
    if (i >= EP * 4) return;
    int e = i >> 2, h = i & 3;
    int d = (e < E) ? g_dst[e] : (e - E);
    float m = fdec(g_mx[d * 4 + h]);
    float a = __expf(g_logit[i] - m);
    g_logit[i] = a;
    atomicAdd(&g_den[d * 4 + h], a);
}

// ---------------- weighted aggregation (warp per edge, atomics into L2) -----
__global__ void k_aggr(int E, int EP){
    int w = (blockIdx.x * blockDim.x + threadIdx.x) >> 5;
    int lane = threadIdx.x & 31;
    if (w >= EP) return;
    int s, d;
    if (w < E){ s = g_src[w]; d = g_dst[w]; }
    else      { s = w - E; d = s; }
    float c = 0.f;
    if (lane < 4) c = g_logit[(size_t)w * 4 + lane] / g_den[d * 4 + lane];
    float c0 = __shfl_sync(~0u, c, 0);
    float c1 = __shfl_sync(~0u, c, 1);
    float c2 = __shfl_sync(~0u, c, 2);
    float c3 = __shfl_sync(~0u, c, 3);
    const float* xls = g_xl + (size_t)s * 128;
    float* od = g_agg + (size_t)d * 128;
    atomicAdd(&od[lane     ], c0 * xls[lane     ]);
    atomicAdd(&od[lane + 32], c1 * xls[lane + 32]);
    atomicAdd(&od[lane + 64], c2 * xls[lane + 64]);
    atomicAdd(&od[lane + 96], c3 * xls[lane + 96]);
}

// ---------------- conv bias + ELU -> h --------------------------------------
__global__ void k_elu(const float* __restrict__ cb, int n){
    int i = blockIdx.x * blockDim.x + threadIdx.x;
    if (i >= n) return;
    float v = g_agg[i] + cb[i & 127];
    g_h[i] = v > 0.f ? v : expm1f(v);
}

// ---------------- LayerNorm + MLP head (warp per node) ----------------------
__global__ void k_final(const float* __restrict__ lng, const float* __restrict__ lnb,
                        const float* __restrict__ h1w, const float* __restrict__ h1b,
                        const float* __restrict__ h2w, const float* __restrict__ h2b,
                        float* __restrict__ out, int N){
    __shared__ float s_w1[128 * 64];
    __shared__ float s_w2[64 * 3];
    int t = threadIdx.x;
    for (int i = t; i < 8192; i += 256) s_w1[i] = h1w[i];
    if (t < 192) s_w2[t] = h2w[t];
    __syncthreads();
    int warp = t >> 5, lane = t & 31;
    int node = blockIdx.x * 8 + warp;
    if (node >= N) return;
    const float* hrow = g_h + (size_t)node * 128;
    float hv[4];
    #pragma unroll
    for (int i = 0; i < 4; i++) hv[i] = hrow[lane + 32 * i];
    float s = hv[0] + hv[1] + hv[2] + hv[3];
    #pragma unroll
    for (int off = 16; off; off >>= 1) s += __shfl_xor_sync(~0u, s, off);
    float mu = s * (1.f / 128.f);
    float sq = 0.f;
    #pragma unroll
    for (int i = 0; i < 4; i++){ float dd = hv[i] - mu; sq += dd * dd; }
    #pragma unroll
    for (int off = 16; off; off >>= 1) sq += __shfl_xor_sync(~0u, sq, off);
    float rs = rsqrtf(sq * (1.f / 128.f) + 1e-5f);
    float y[4];
    #pragma unroll
    for (int i = 0; i < 4; i++){
        int c = lane + 32 * i;
        y[i] = (hv[i] - mu) * rs * lng[c] + lnb[c];
    }
    float a0 = h1b[lane], a1 = h1b[lane + 32];
    #pragma unroll
    for (int k = 0; k < 128; k++){
        float yv = __shfl_sync(~0u, y[k >> 5], k & 31);
        a0 = fmaf(yv, s_w1[k * 64 + lane     ], a0);
        a1 = fmaf(yv, s_w1[k * 64 + lane + 32], a1);
    }
    a0 = fmaxf(a0, 0.f); a1 = fmaxf(a1, 0.f);
    float p0 = a0 * s_w2[lane * 3 + 0] + a1 * s_w2[(lane + 32) * 3 + 0];
    float p1 = a0 * s_w2[lane * 3 + 1] + a1 * s_w2[(lane + 32) * 3 + 1];
    float p2 = a0 * s_w2[lane * 3 + 2] + a1 * s_w2[(lane + 32) * 3 + 2];
    #pragma unroll
    for (int off = 16; off; off >>= 1){
        p0 += __shfl_xor_sync(~0u, p0, off);
        p1 += __shfl_xor_sync(~0u, p1, off);
        p2 += __shfl_xor_sync(~0u, p2, off);
    }
    if (lane == 0){
        out[node * 3 + 0] = p0 + h2b[0];
        out[node * 3 + 1] = p1 + h2b[1];
        out[node * 3 + 2] = p2 + h2b[2];
    }
}

// ---------------- host orchestration ----------------------------------------
extern "C" void kernel_launch(void* const* d_in, const int* in_sizes, int n_in,
                              void* d_out, int out_size){
    const float* x     = (const float*)d_in[0];
    const int*   eidx  = (const int*)d_in[1];     // int32 or int64 (detected on device)
    const float* eattr = (const float*)d_in[2];
    const float* in_w  = (const float*)d_in[3];
    const float* in_b  = (const float*)d_in[4];
    const float* Wl    = (const float*)d_in[5];
    const float* bl    = (const float*)d_in[6];
    const float* Wr    = (const float*)d_in[7];
    const float* br    = (const float*)d_in[8];
    const float* We    = (const float*)d_in[9];
    const float* att   = (const float*)d_in[10];
    const float* cb    = (const float*)d_in[11];
    const float* lng   = (const float*)d_in[12];
    const float* lnb   = (const float*)d_in[13];
    const float* h1w   = (const float*)d_in[14];
    const float* h1b   = (const float*)d_in[15];
    const float* h2w   = (const float*)d_in[16];
    const float* h2b   = (const float*)d_in[17];
    float* out = (float*)d_out;

    int N  = in_sizes[0] / 128;
    int E  = in_sizes[1] / 2;   // element count is 2E for both int32 and int64
    int EP = E + N;

    // normalize edge indices to int32 g_src/g_dst
    k_detect<<<1, 256>>>(eidx);
    k_convert<<<(E + 255) / 256, 256>>>(eidx, E);

    // self-loop attrs (mean of incoming edge_attr)
    k_zero_pre<<<(N * 16 + 255) / 256, 256>>>(N);
    k_deg<<<(E * 16 + 255) / 256, 256>>>(eattr, E);
    k_loopdiv<<<(N * 16 + 255) / 256, 256>>>(N);

    // input projection -> g_h
    k_gemm128<<<(N + 15) / 16, 128>>>(x, in_w, in_b, N);

    for (int l = 0; l < 2; l++){
        const float* Wl_l  = Wl  + (size_t)l * 128 * 128;
        const float* bl_l  = bl  + (size_t)l * 128;
        const float* Wr_l  = Wr  + (size_t)l * 128 * 128;
        const float* br_l  = br  + (size_t)l * 128;
        const float* We_l  = We  + (size_t)l * 16 * 128;
        const float* att_l = att + (size_t)l * 128;
        const float* cb_l  = cb  + (size_t)l * 128;

        k_dualgemm<<<(N + 15) / 16, 128>>>(Wl_l, bl_l, Wr_l, br_l, N);
        k_zero_layer<<<(N * 32 + 255) / 256, 256>>>(N);
        k_logit<<<4096, 256>>>(eattr, We_l, att_l, E, EP);
        k_exp<<<(EP * 4 + 255) / 256, 256>>>(E, EP);
        k_aggr<<<(EP * 32 + 255) / 256, 256>>>(E, EP);
        k_elu<<<(N * 128 + 255) / 256, 256>>>(cb_l, N * 128);
    }

    k_final<<<(N + 7) / 8, 256>>>(lng, lnb, h1w, h1b, h2w, h2b, out, N);
}

// round 4
// speedup vs baseline: 1.5144x; 1.5144x over previous
#include <cuda_runtime.h>
#include <cstdint>

#define CN 50000
#define CE 600000
#define CEP (CE + CN)

// ---------------- device scratch (static: no allocations allowed) -----------
__device__ __align__(16) float g_h   [(size_t)CN * 128];
__device__ __align__(16) float g_xl  [(size_t)CN * 128];
__device__ __align__(16) float g_xr  [(size_t)CN * 128];
__device__ __align__(16) float g_loop[(size_t)CN * 16];
__device__ int g_is64;
__device__ __align__(16) int g_src[CE];
__device__ __align__(16) int g_dst[CE];
__device__ __align__(16) int g_cnt[CN];
__device__ __align__(16) int g_off[CN + 1];
__device__ __align__(16) int g_cur[CN];
__device__ __align__(16) int g_csr_eid[CEP];
__device__ __align__(16) int g_csr_src[CEP];

// ---------------- index dtype detection + normalization ---------------------
__global__ void k_detect(const int* __restrict__ idx){
    __shared__ int s_or;
    if (threadIdx.x == 0) s_or = 0;
    __syncthreads();
    int v = 0;
    for (int i = threadIdx.x; i < 1024; i += blockDim.x) v |= idx[2 * i + 1];
    atomicOr(&s_or, v);
    __syncthreads();
    if (threadIdx.x == 0) g_is64 = (s_or == 0) ? 1 : 0;
}

__global__ void k_convert(const int* __restrict__ idx, int E){
    int e = blockIdx.x * blockDim.x + threadIdx.x;
    if (e >= E) return;
    if (g_is64){
        g_src[e] = idx[2 * e];
        g_dst[e] = idx[2 * (E + e)];
    } else {
        g_src[e] = idx[e];
        g_dst[e] = idx[E + e];
    }
}

// ---------------- CSR build (by destination, self-loop included) -------------
__global__ void k_initcnt(int N){
    int i = blockIdx.x * blockDim.x + threadIdx.x;
    if (i < N) g_cnt[i] = 1;          // self loop pre-counted
}

__global__ void k_hist(int E){
    int e = blockIdx.x * blockDim.x + threadIdx.x;
    if (e < E) atomicAdd(&g_cnt[g_dst[e]], 1);
}

// single-block exclusive scan over g_cnt -> g_off (warp-scan based)
__global__ void k_scan(int N){
    __shared__ int warpsum[32];
    __shared__ int carry_s;
    int tid = threadIdx.x, lane = tid & 31, wid = tid >> 5;
    if (tid == 0) carry_s = 0;
    __syncthreads();
    for (int base = 0; base < N; base += 1024){
        int i = base + tid;
        int v = (i < N) ? g_cnt[i] : 0;
        int x = v;
        #pragma unroll
        for (int off = 1; off < 32; off <<= 1){
            int t = __shfl_up_sync(~0u, x, off);
            if (lane >= off) x += t;
        }
        if (lane == 31) warpsum[wid] = x;
        __syncthreads();
        if (wid == 0){
            int w = warpsum[lane];
            #pragma unroll
            for (int off = 1; off < 32; off <<= 1){
                int t = __shfl_up_sync(~0u, w, off);
                if (lane >= off) w += t;
            }
            warpsum[lane] = w;
        }
        __syncthreads();
        int carry = carry_s;
        int wb = (wid > 0) ? warpsum[wid - 1] : 0;
        if (i < N) g_off[i] = carry + wb + x - v;
        __syncthreads();
        if (tid == 1023) carry_s = carry + warpsum[31];
        __syncthreads();
    }
    if (threadIdx.x == 0) g_off[N] = carry_s;
}

__global__ void k_copyoff(int N){
    int i = blockIdx.x * blockDim.x + threadIdx.x;
    if (i < N) g_cur[i] = g_off[i];
}

__global__ void k_scatter(int E, int EP){
    int e = blockIdx.x * blockDim.x + threadIdx.x;
    if (e >= EP) return;
    int d, s;
    if (e < E){ d = g_dst[e]; s = g_src[e]; }
    else      { d = e - E;    s = d; }
    int pos = atomicAdd(&g_cur[d], 1);
    g_csr_eid[pos] = e;
    g_csr_src[pos] = s;
}

// ---------------- self-loop attr = mean of incoming edge_attr (CSR, no atomics)
__global__ void k_loopattr(const float* __restrict__ ea, int E, int N){
    int lane = threadIdx.x & 31;
    int node = (blockIdx.x * blockDim.x + threadIdx.x) >> 5;
    if (node >= N) return;
    int beg = g_off[node], end = g_off[node + 1];
    float sum = 0.f;
    for (int p = beg; p < end; p++){
        int eid = g_csr_eid[p];
        if (eid < E && lane < 16) sum += ea[(size_t)eid * 16 + lane];
    }
    float inv = 1.f / fmaxf((float)(end - beg - 1), 1.f);
    if (lane < 16) g_loop[node * 16 + lane] = sum * inv;
}

// ---------------- GEMM: g_h[M,128] = A[M,128] @ W[128,128] + b --------------
__global__ void k_gemm128(const float* __restrict__ A, const float* __restrict__ W,
                          const float* __restrict__ b, int M){
    __shared__ float4 sA[512];
    int row0 = blockIdx.x * 16;
    int t = threadIdx.x;
    const float4* A4 = (const float4*)A;
    for (int i = t; i < 512; i += 128){
        int r = i >> 5, c = i & 31;
        sA[i] = (row0 + r < M) ? A4[(size_t)(row0 + r) * 32 + c] : make_float4(0,0,0,0);
    }
    __syncthreads();
    float acc[16];
    float bv = b[t];
    #pragma unroll
    for (int r = 0; r < 16; r++) acc[r] = bv;
    for (int k4 = 0; k4 < 32; k4++){
        int kb = k4 * 512 + t;
        float w0 = W[kb], w1 = W[kb + 128], w2 = W[kb + 256], w3 = W[kb + 384];
        #pragma unroll
        for (int r = 0; r < 16; r++){
            float4 a = sA[r * 32 + k4];
            acc[r] = fmaf(a.x, w0, acc[r]);
            acc[r] = fmaf(a.y, w1, acc[r]);
            acc[r] = fmaf(a.z, w2, acc[r]);
            acc[r] = fmaf(a.w, w3, acc[r]);
        }
    }
    #pragma unroll
    for (int r = 0; r < 16; r++)
        if (row0 + r < M) g_h[(size_t)(row0 + r) * 128 + t] = acc[r];
}

__global__ void k_dualgemm(const float* __restrict__ Wl, const float* __restrict__ bl,
                           const float* __restrict__ Wr, const float* __restrict__ br, int M){
    __shared__ float4 sA[512];
    int row0 = blockIdx.x * 16;
    int t = threadIdx.x;
    const float4* A4 = (const float4*)g_h;
    for (int i = t; i < 512; i += 128){
        int r = i >> 5, c = i & 31;
        sA[i] = (row0 + r < M) ? A4[(size_t)(row0 + r) * 32 + c] : make_float4(0,0,0,0);
    }
    __syncthreads();
    float accL[16], accR[16];
    float bL = bl[t], bR = br[t];
    #pragma unroll
    for (int r = 0; r < 16; r++){ accL[r] = bL; accR[r] = bR; }
    for (int k4 = 0; k4 < 32; k4++){
        int kb = k4 * 512 + t;
        float l0 = Wl[kb], l1 = Wl[kb + 128], l2 = Wl[kb + 256], l3 = Wl[kb + 384];
        float r0 = Wr[kb], r1 = Wr[kb + 128], r2 = Wr[kb + 256], r3 = Wr[kb + 384];
        #pragma unroll
        for (int r = 0; r < 16; r++){
            float4 a = sA[r * 32 + k4];
            accL[r] = fmaf(a.x, l0, accL[r]);
            accL[r] = fmaf(a.y, l1, accL[r]);
            accL[r] = fmaf(a.z, l2, accL[r]);
            accL[r] = fmaf(a.w, l3, accL[r]);
            accR[r] = fmaf(a.x, r0, accR[r]);
            accR[r] = fmaf(a.y, r1, accR[r]);
            accR[r] = fmaf(a.z, r2, accR[r]);
            accR[r] = fmaf(a.w, r3, accR[r]);
        }
    }
    #pragma unroll
    for (int r = 0; r < 16; r++){
        if (row0 + r < M){
            g_xl[(size_t)(row0 + r) * 128 + t] = accL[r];
            g_xr[(size_t)(row0 + r) * 128 + t] = accR[r];
        }
    }
}

// ---------------- fused edge phase: logits + online softmax + aggregate + ELU
// One warp per destination node; zero float atomics.
__global__ void k_edge_fused(const float* __restrict__ ea, const float* __restrict__ We_l,
                             const float* __restrict__ att_l, const float* __restrict__ cb_l,
                             int E, int N){
    int lane = threadIdx.x & 31;
    int node = (blockIdx.x * blockDim.x + threadIdx.x) >> 5;
    if (node >= N) return;

    float we[4][16], attv[4];
    #pragma unroll
    for (int h = 0; h < 4; h++){
        int col = lane + 32 * h;
        attv[h] = att_l[col];
        #pragma unroll
        for (int j = 0; j < 16; j++) we[h][j] = We_l[j * 128 + col];
    }

    int beg = g_off[node], end = g_off[node + 1];
    float xrd[4];
    #pragma unroll
    for (int h = 0; h < 4; h++) xrd[h] = g_xr[(size_t)node * 128 + lane + 32 * h];

    float mxv[4] = {-3.0e38f, -3.0e38f, -3.0e38f, -3.0e38f};
    float den[4] = {0.f, 0.f, 0.f, 0.f};
    float acc[4] = {0.f, 0.f, 0.f, 0.f};

    for (int p = beg; p < end; p++){
        int eid = g_csr_eid[p];
        int s   = g_csr_src[p];
        const float4* ap = (eid < E) ? (const float4*)(ea + (size_t)eid * 16)
                                     : (const float4*)(g_loop + (size_t)(eid - E) * 16);
        float4 q0 = ap[0], q1 = ap[1], q2 = ap[2], q3 = ap[3];
        float av[16] = {q0.x,q0.y,q0.z,q0.w, q1.x,q1.y,q1.z,q1.w,
                        q2.x,q2.y,q2.z,q2.w, q3.x,q3.y,q3.z,q3.w};
        const float* xls = g_xl + (size_t)s * 128;
        float xsv[4], lg[4];
        #pragma unroll
        for (int h = 0; h < 4; h++){
            float eev = 0.f;
            #pragma unroll
            for (int j = 0; j < 16; j++) eev = fmaf(av[j], we[h][j], eev);
            float xv = xls[lane + 32 * h];
            xsv[h] = xv;
            float m = xv + xrd[h] + eev;
            m = m > 0.f ? m : 0.2f * m;       // LeakyReLU(0.2)
            lg[h] = m * attv[h];
        }
        #pragma unroll
        for (int off = 16; off; off >>= 1){
            lg[0] += __shfl_xor_sync(~0u, lg[0], off);
            lg[1] += __shfl_xor_sync(~0u, lg[1], off);
            lg[2] += __shfl_xor_sync(~0u, lg[2], off);
            lg[3] += __shfl_xor_sync(~0u, lg[3], off);
        }
        #pragma unroll
        for (int h = 0; h < 4; h++){
            float nm = fmaxf(mxv[h], lg[h]);
            float sc = __expf(mxv[h] - nm);   // 0 on first iter, 1 if no new max
            float w  = __expf(lg[h]  - nm);
            den[h] = den[h] * sc + w;
            acc[h] = acc[h] * sc + w * xsv[h];
            mxv[h] = nm;
        }
    }
    #pragma unroll
    for (int h = 0; h < 4; h++){
        int col = lane + 32 * h;
        float v = acc[h] / den[h] + cb_l[col];
        g_h[(size_t)node * 128 + col] = v > 0.f ? v : expm1f(v);   // ELU
    }
}

// ---------------- LayerNorm + MLP head (warp per node) ----------------------
__global__ void k_final(const float* __restrict__ lng, const float* __restrict__ lnb,
                        const float* __restrict__ h1w, const float* __restrict__ h1b,
                        const float* __restrict__ h2w, const float* __restrict__ h2b,
                        float* __restrict__ out, int N){
    __shared__ float s_w1[128 * 64];
    __shared__ float s_w2[64 * 3];
    int t = threadIdx.x;
    for (int i = t; i < 8192; i += 256) s_w1[i] = h1w[i];
    if (t < 192) s_w2[t] = h2w[t];
    __syncthreads();
    int warp = t >> 5, lane = t & 31;
    int node = blockIdx.x * 8 + warp;
    if (node >= N) return;
    const float* hrow = g_h + (size_t)node * 128;
    float hv[4];
    #pragma unroll
    for (int i = 0; i < 4; i++) hv[i] = hrow[lane + 32 * i];
    float s = hv[0] + hv[1] + hv[2] + hv[3];
    #pragma unroll
    for (int off = 16; off; off >>= 1) s += __shfl_xor_sync(~0u, s, off);
    float mu = s * (1.f / 128.f);
    float sq = 0.f;
    #pragma unroll
    for (int i = 0; i < 4; i++){ float dd = hv[i] - mu; sq += dd * dd; }
    #pragma unroll
    for (int off = 16; off; off >>= 1) sq += __shfl_xor_sync(~0u, sq, off);
    float rs = rsqrtf(sq * (1.f / 128.f) + 1e-5f);
    float y[4];
    #pragma unroll
    for (int i = 0; i < 4; i++){
        int c = lane + 32 * i;
        y[i] = (hv[i] - mu) * rs * lng[c] + lnb[c];
    }
    float a0 = h1b[lane], a1 = h1b[lane + 32];
    #pragma unroll
    for (int k = 0; k < 128; k++){
        float yv = __shfl_sync(~0u, y[k >> 5], k & 31);
        a0 = fmaf(yv, s_w1[k * 64 + lane     ], a0);
        a1 = fmaf(yv, s_w1[k * 64 + lane + 32], a1);
    }
    a0 = fmaxf(a0, 0.f); a1 = fmaxf(a1, 0.f);
    float p0 = a0 * s_w2[lane * 3 + 0] + a1 * s_w2[(lane + 32) * 3 + 0];
    float p1 = a0 * s_w2[lane * 3 + 1] + a1 * s_w2[(lane + 32) * 3 + 1];
    float p2 = a0 * s_w2[lane * 3 + 2] + a1 * s_w2[(lane + 32) * 3 + 2];
    #pragma unroll
    for (int off = 16; off; off >>= 1){
        p0 += __shfl_xor_sync(~0u, p0, off);
        p1 += __shfl_xor_sync(~0u, p1, off);
        p2 += __shfl_xor_sync(~0u, p2, off);
    }
    if (lane == 0){
        out[node * 3 + 0] = p0 + h2b[0];
        out[node * 3 + 1] = p1 + h2b[1];
        out[node * 3 + 2] = p2 + h2b[2];
    }
}

// ---------------- host orchestration ----------------------------------------
extern "C" void kernel_launch(void* const* d_in, const int* in_sizes, int n_in,
                              void* d_out, int out_size){
    const float* x     = (const float*)d_in[0];
    const int*   eidx  = (const int*)d_in[1];
    const float* eattr = (const float*)d_in[2];
    const float* in_w  = (const float*)d_in[3];
    const float* in_b  = (const float*)d_in[4];
    const float* Wl    = (const float*)d_in[5];
    const float* bl    = (const float*)d_in[6];
    const float* Wr    = (const float*)d_in[7];
    const float* br    = (const float*)d_in[8];
    const float* We    = (const float*)d_in[9];
    const float* att   = (const float*)d_in[10];
    const float* cb    = (const float*)d_in[11];
    const float* lng   = (const float*)d_in[12];
    const float* lnb   = (const float*)d_in[13];
    const float* h1w   = (const float*)d_in[14];
    const float* h1b   = (const float*)d_in[15];
    const float* h2w   = (const float*)d_in[16];
    const float* h2b   = (const float*)d_in[17];
    float* out = (float*)d_out;

    int N  = in_sizes[0] / 128;
    int E  = in_sizes[1] / 2;
    int EP = E + N;

    // edge index normalization
    k_detect<<<1, 256>>>(eidx);
    k_convert<<<(E + 255) / 256, 256>>>(eidx, E);

    // CSR build (by destination)
    k_initcnt<<<(N + 255) / 256, 256>>>(N);
    k_hist<<<(E + 255) / 256, 256>>>(E);
    k_scan<<<1, 1024>>>(N);
    k_copyoff<<<(N + 255) / 256, 256>>>(N);
    k_scatter<<<(EP + 255) / 256, 256>>>(E, EP);

    // self-loop attrs
    k_loopattr<<<(N * 32 + 255) / 256, 256>>>(eattr, E, N);

    // input projection -> g_h
    k_gemm128<<<(N + 15) / 16, 128>>>(x, in_w, in_b, N);

    for (int l = 0; l < 2; l++){
        const float* Wl_l  = Wl  + (size_t)l * 128 * 128;
        const float* bl_l  = bl  + (size_t)l * 128;
        const float* Wr_l  = Wr  + (size_t)l * 128 * 128;
        const float* br_l  = br  + (size_t)l * 128;
        const float* We_l  = We  + (size_t)l * 16 * 128;
        const float* att_l = att + (size_t)l * 128;
        const float* cb_l  = cb  + (size_t)l * 128;

        k_dualgemm<<<(N + 15) / 16, 128>>>(Wl_l, bl_l, Wr_l, br_l, N);
        k_edge_fused<<<(N * 32 + 255) / 256, 256>>>(eattr, We_l, att_l, cb_l, E, N);
    }

    k_final<<<(N + 7) / 8, 256>>>(lng, lnb, h1w, h1b, h2w, h2b, out, N);
}

// round 5
// speedup vs baseline: 1.6768x; 1.1073x over previous
#include <cuda_runtime.h>
#include <cstdint>

#define CN 50000
#define CE 600000
#define CEP (CE + CN)

// ---------------- device scratch (static: no allocations allowed) -----------
__device__ __align__(16) float g_h   [(size_t)CN * 128];
__device__ __align__(16) float g_xl  [(size_t)CN * 128];
__device__ __align__(16) float g_xr  [(size_t)CN * 128];
__device__ __align__(16) float g_loop[(size_t)CN * 16];
__device__ int g_is64;
__device__ __align__(16) int g_src[CE];
__device__ __align__(16) int g_dst[CE];
__device__ __align__(16) int g_cnt[CN];
__device__ __align__(16) int g_off[CN + 1];
__device__ __align__(16) int g_cur[CN];
__device__ __align__(16) int g_csr_eid[CEP];
__device__ __align__(16) int g_csr_src[CEP];
__device__ int g_bsum[64];
__device__ int g_bpre[64];
__device__ int g_total;

// ---------------- f32x2 packed helpers (sm_10x) ------------------------------
__device__ __forceinline__ unsigned long long pk2(float lo, float hi){
    unsigned long long r;
    asm("mov.b64 %0, {%1,%2};" : "=l"(r) : "f"(lo), "f"(hi));
    return r;
}
__device__ __forceinline__ void upk2(unsigned long long v, float& lo, float& hi){
    asm("mov.b64 {%0,%1}, %2;" : "=f"(lo), "=f"(hi) : "l"(v));
}
__device__ __forceinline__ unsigned long long fma2(unsigned long long a, unsigned long long b, unsigned long long c){
    unsigned long long d;
    asm("fma.rn.f32x2 %0, %1, %2, %3;" : "=l"(d) : "l"(a), "l"(b), "l"(c));
    return d;
}
__device__ __forceinline__ unsigned long long add2(unsigned long long a, unsigned long long b){
    unsigned long long d;
    asm("add.rn.f32x2 %0, %1, %2;" : "=l"(d) : "l"(a), "l"(b));
    return d;
}
__device__ __forceinline__ unsigned long long mul2(unsigned long long a, unsigned long long b){
    unsigned long long d;
    asm("mul.rn.f32x2 %0, %1, %2;" : "=l"(d) : "l"(a), "l"(b));
    return d;
}

// ---------------- index dtype detection + normalization ---------------------
__global__ void k_detect(const int* __restrict__ idx){
    __shared__ int s_or;
    if (threadIdx.x == 0) s_or = 0;
    __syncthreads();
    int v = 0;
    for (int i = threadIdx.x; i < 1024; i += blockDim.x) v |= idx[2 * i + 1];
    atomicOr(&s_or, v);
    __syncthreads();
    if (threadIdx.x == 0) g_is64 = (s_or == 0) ? 1 : 0;
}

__global__ void k_convert(const int* __restrict__ idx, int E){
    int e = blockIdx.x * blockDim.x + threadIdx.x;
    if (e >= E) return;
    if (g_is64){
        g_src[e] = idx[2 * e];
        g_dst[e] = idx[2 * (E + e)];
    } else {
        g_src[e] = idx[e];
        g_dst[e] = idx[E + e];
    }
}

// ---------------- CSR build (by destination, self-loop included) -------------
__global__ void k_initcnt(int N){
    int i = blockIdx.x * blockDim.x + threadIdx.x;
    if (i < N) g_cnt[i] = 1;          // self loop pre-counted
}

__global__ void k_hist(int E){
    int e = blockIdx.x * blockDim.x + threadIdx.x;
    if (e < E) atomicAdd(&g_cnt[g_dst[e]], 1);
}

// multi-block scan: pass 1 (per-block exclusive scan + block sums)
__global__ void k_scan1(int N){
    __shared__ int warpsum[32];
    int tid = threadIdx.x, lane = tid & 31, wid = tid >> 5;
    int i = blockIdx.x * 1024 + tid;
    int v = (i < N) ? g_cnt[i] : 0;
    int x = v;
    #pragma unroll
    for (int off = 1; off < 32; off <<= 1){
        int t = __shfl_up_sync(~0u, x, off);
        if (lane >= off) x += t;
    }
    if (lane == 31) warpsum[wid] = x;
    __syncthreads();
    if (wid == 0){
        int w = warpsum[lane];
        #pragma unroll
        for (int off = 1; off < 32; off <<= 1){
            int t = __shfl_up_sync(~0u, w, off);
            if (lane >= off) w += t;
        }
        warpsum[lane] = w;
    }
    __syncthreads();
    int wb = (wid > 0) ? warpsum[wid - 1] : 0;
    if (i < N) g_off[i] = wb + x - v;
    if (tid == 1023) g_bsum[blockIdx.x] = wb + x;
}

// pass 2: single warp scans block sums
__global__ void k_scan2(int NB){
    int lane = threadIdx.x;
    int acc = 0;
    for (int base = 0; base < NB; base += 32){
        int idx = base + lane;
        int v = (idx < NB) ? g_bsum[idx] : 0;
        int x = v;
        #pragma unroll
        for (int off = 1; off < 32; off <<= 1){
            int t = __shfl_up_sync(~0u, x, off);
            if (lane >= off) x += t;
        }
        if (idx < NB) g_bpre[idx] = acc + x - v;
        acc += __shfl_sync(~0u, x, 31);
    }
    if (lane == 0) g_total = acc;
}

// pass 3: add block prefixes
__global__ void k_scan3(int N){
    int i = blockIdx.x * blockDim.x + threadIdx.x;
    if (i < N) g_off[i] += g_bpre[i >> 10];
    if (i == 0) g_off[N] = g_total;
}

__global__ void k_copyoff(int N){
    int i = blockIdx.x * blockDim.x + threadIdx.x;
    if (i < N) g_cur[i] = g_off[i];
}

__global__ void k_scatter(int E, int EP){
    int e = blockIdx.x * blockDim.x + threadIdx.x;
    if (e >= EP) return;
    int d, s;
    if (e < E){ d = g_dst[e]; s = g_src[e]; }
    else      { d = e - E;    s = d; }
    int pos = atomicAdd(&g_cur[d], 1);
    g_csr_eid[pos] = e;
    g_csr_src[pos] = s;
}

// ---------------- self-loop attr = mean of incoming edge_attr (CSR, no atomics)
__global__ void k_loopattr(const float* __restrict__ ea, int E, int N){
    int lane = threadIdx.x & 31;
    int node = (blockIdx.x * blockDim.x + threadIdx.x) >> 5;
    if (node >= N) return;
    int beg = g_off[node], end = g_off[node + 1];
    float sum = 0.f;
    for (int p = beg; p < end; p++){
        int eid = g_csr_eid[p];
        if (eid < E && lane < 16) sum += ea[(size_t)eid * 16 + lane];
    }
    float inv = 1.f / fmaxf((float)(end - beg - 1), 1.f);
    if (lane < 16) g_loop[node * 16 + lane] = sum * inv;
}

// ---------------- GEMM (f32x2): g_h[M,128] = A[M,128] @ W[128,128] + b ------
__global__ void k_gemm128(const float* __restrict__ A, const float* __restrict__ W,
                          const float* __restrict__ b, int M){
    __shared__ ulonglong2 sA[512];       // 16 rows x 32 x (4 floats)
    int row0 = blockIdx.x * 16;
    int t = threadIdx.x;
    const ulonglong2* A4 = (const ulonglong2*)A;
    for (int i = t; i < 512; i += 128){
        int r = i >> 5, c = i & 31;
        ulonglong2 z; z.x = 0ULL; z.y = 0ULL;
        sA[i] = (row0 + r < M) ? A4[(size_t)(row0 + r) * 32 + c] : z;
    }
    __syncthreads();
    unsigned long long acc[16];
    #pragma unroll
    for (int r = 0; r < 16; r++) acc[r] = 0ULL;
    for (int k4 = 0; k4 < 32; k4++){
        int kb = k4 * 512 + t;
        float w0 = W[kb], w1 = W[kb + 128], w2 = W[kb + 256], w3 = W[kb + 384];
        unsigned long long w01 = pk2(w0, w1), w23 = pk2(w2, w3);
        #pragma unroll
        for (int r = 0; r < 16; r++){
            ulonglong2 a = sA[r * 32 + k4];
            acc[r] = fma2(a.x, w01, acc[r]);
            acc[r] = fma2(a.y, w23, acc[r]);
        }
    }
    float bv = b[t];
    #pragma unroll
    for (int r = 0; r < 16; r++){
        if (row0 + r < M){
            float lo, hi; upk2(acc[r], lo, hi);
            g_h[(size_t)(row0 + r) * 128 + t] = lo + hi + bv;
        }
    }
}

// Fused dual GEMM (f32x2): xl = h@Wl+bl, xr = h@Wr+br
__global__ void k_dualgemm(const float* __restrict__ Wl, const float* __restrict__ bl,
                           const float* __restrict__ Wr, const float* __restrict__ br, int M){
    __shared__ ulonglong2 sA[512];
    int row0 = blockIdx.x * 16;
    int t = threadIdx.x;
    const ulonglong2* A4 = (const ulonglong2*)g_h;
    for (int i = t; i < 512; i += 128){
        int r = i >> 5, c = i & 31;
        ulonglong2 z; z.x = 0ULL; z.y = 0ULL;
        sA[i] = (row0 + r < M) ? A4[(size_t)(row0 + r) * 32 + c] : z;
    }
    __syncthreads();
    unsigned long long accL[16], accR[16];
    #pragma unroll
    for (int r = 0; r < 16; r++){ accL[r] = 0ULL; accR[r] = 0ULL; }
    for (int k4 = 0; k4 < 32; k4++){
        int kb = k4 * 512 + t;
        float l0 = Wl[kb], l1 = Wl[kb + 128], l2 = Wl[kb + 256], l3 = Wl[kb + 384];
        float r0 = Wr[kb], r1 = Wr[kb + 128], r2 = Wr[kb + 256], r3 = Wr[kb + 384];
        unsigned long long l01 = pk2(l0, l1), l23 = pk2(l2, l3);
        unsigned long long r01 = pk2(r0, r1), r23 = pk2(r2, r3);
        #pragma unroll
        for (int r = 0; r < 16; r++){
            ulonglong2 a = sA[r * 32 + k4];
            accL[r] = fma2(a.x, l01, accL[r]);
            accL[r] = fma2(a.y, l23, accL[r]);
            accR[r] = fma2(a.x, r01, accR[r]);
            accR[r] = fma2(a.y, r23, accR[r]);
        }
    }
    float bL = bl[t], bR = br[t];
    #pragma unroll
    for (int r = 0; r < 16; r++){
        if (row0 + r < M){
            float lo, hi;
            upk2(accL[r], lo, hi);
            g_xl[(size_t)(row0 + r) * 128 + t] = lo + hi + bL;
            upk2(accR[r], lo, hi);
            g_xr[(size_t)(row0 + r) * 128 + t] = lo + hi + bR;
        }
    }
}

// ---------------- fused edge phase: logits + online softmax + aggregate + ELU
// Warp per destination node. Lane owns 4 channels (col = lane*4), head = lane>>3.
// Logit reduction = 3-step butterfly over the 8 lanes of the head group.
__global__ void k_edge_fused(const float* __restrict__ ea, const float* __restrict__ We_l,
                             const float* __restrict__ att_l, const float* __restrict__ cb_l,
                             int E, int N){
    int lane = threadIdx.x & 31;
    int node = (blockIdx.x * blockDim.x + threadIdx.x) >> 5;
    if (node >= N) return;

    float4 attv = ((const float4*)att_l)[lane];
    unsigned long long we01[16], we23[16];
    #pragma unroll
    for (int j = 0; j < 16; j++){
        float4 w = ((const float4*)(We_l + j * 128))[lane];
        we01[j] = pk2(w.x, w.y);
        we23[j] = pk2(w.z, w.w);
    }

    ulonglong2 xr = ((const ulonglong2*)(g_xr + (size_t)node * 128))[lane];
    int beg = g_off[node], end = g_off[node + 1];

    float mx = -3.0e38f, den = 0.f;
    unsigned long long acc01 = 0ULL, acc23 = 0ULL;

    for (int p = beg; p < end; p++){
        int eid = g_csr_eid[p];
        int s   = g_csr_src[p];
        const float4* ap = (eid < E) ? (const float4*)(ea + (size_t)eid * 16)
                                     : (const float4*)(g_loop + (size_t)(eid - E) * 16);
        float4 q0 = ap[0], q1 = ap[1], q2 = ap[2], q3 = ap[3];
        float av[16] = {q0.x,q0.y,q0.z,q0.w, q1.x,q1.y,q1.z,q1.w,
                        q2.x,q2.y,q2.z,q2.w, q3.x,q3.y,q3.z,q3.w};
        ulonglong2 xl = ((const ulonglong2*)(g_xl + (size_t)s * 128))[lane];

        unsigned long long m01 = add2(xl.x, xr.x);
        unsigned long long m23 = add2(xl.y, xr.y);
        #pragma unroll
        for (int j = 0; j < 16; j++){
            unsigned long long a2 = pk2(av[j], av[j]);
            m01 = fma2(a2, we01[j], m01);
            m23 = fma2(a2, we23[j], m23);
        }
        float m0, m1, m2, m3;
        upk2(m01, m0, m1); upk2(m23, m2, m3);
        m0 = m0 > 0.f ? m0 : 0.2f * m0;
        m1 = m1 > 0.f ? m1 : 0.2f * m1;
        m2 = m2 > 0.f ? m2 : 0.2f * m2;
        m3 = m3 > 0.f ? m3 : 0.2f * m3;
        float lg = fmaf(m0, attv.x, fmaf(m1, attv.y, fmaf(m2, attv.z, m3 * attv.w)));
        lg += __shfl_xor_sync(~0u, lg, 1);
        lg += __shfl_xor_sync(~0u, lg, 2);
        lg += __shfl_xor_sync(~0u, lg, 4);

        float nm = fmaxf(mx, lg);
        float sc = __expf(mx - nm);
        float w  = __expf(lg - nm);
        den = den * sc + w;
        unsigned long long sc2 = pk2(sc, sc);
        unsigned long long w2  = pk2(w, w);
        acc01 = fma2(acc01, sc2, mul2(w2, xl.x));
        acc23 = fma2(acc23, sc2, mul2(w2, xl.y));
        mx = nm;
    }

    float a0, a1, a2, a3;
    upk2(acc01, a0, a1); upk2(acc23, a2, a3);
    float4 cbv = ((const float4*)cb_l)[lane];
    float inv = 1.f / den;
    float v0 = fmaf(a0, inv, cbv.x);
    float v1 = fmaf(a1, inv, cbv.y);
    float v2 = fmaf(a2, inv, cbv.z);
    float v3 = fmaf(a3, inv, cbv.w);
    float4 o;
    o.x = v0 > 0.f ? v0 : expm1f(v0);
    o.y = v1 > 0.f ? v1 : expm1f(v1);
    o.z = v2 > 0.f ? v2 : expm1f(v2);
    o.w = v3 > 0.f ? v3 : expm1f(v3);
    ((float4*)(g_h + (size_t)node * 128))[lane] = o;
}

// ---------------- LayerNorm + MLP head (warp per node) ----------------------
__global__ void k_final(const float* __restrict__ lng, const float* __restrict__ lnb,
                        const float* __restrict__ h1w, const float* __restrict__ h1b,
                        const float* __restrict__ h2w, const float* __restrict__ h2b,
                        float* __restrict__ out, int N){
    __shared__ float s_w1[128 * 64];
    __shared__ float s_w2[64 * 3];
    int t = threadIdx.x;
    for (int i = t; i < 8192; i += 256) s_w1[i] = h1w[i];
    if (t < 192) s_w2[t] = h2w[t];
    __syncthreads();
    int warp = t >> 5, lane = t & 31;
    int node = blockIdx.x * 8 + warp;
    if (node >= N) return;
    const float* hrow = g_h + (size_t)node * 128;
    float hv[4];
    #pragma unroll
    for (int i = 0; i < 4; i++) hv[i] = hrow[lane + 32 * i];
    float s = hv[0] + hv[1] + hv[2] + hv[3];
    #pragma unroll
    for (int off = 16; off; off >>= 1) s += __shfl_xor_sync(~0u, s, off);
    float mu = s * (1.f / 128.f);
    float sq = 0.f;
    #pragma unroll
    for (int i = 0; i < 4; i++){ float dd = hv[i] - mu; sq += dd * dd; }
    #pragma unroll
    for (int off = 16; off; off >>= 1) sq += __shfl_xor_sync(~0u, sq, off);
    float rs = rsqrtf(sq * (1.f / 128.f) + 1e-5f);
    float y[4];
    #pragma unroll
    for (int i = 0; i < 4; i++){
        int c = lane + 32 * i;
        y[i] = (hv[i] - mu) * rs * lng[c] + lnb[c];
    }
    float a0 = h1b[lane], a1 = h1b[lane + 32];
    #pragma unroll
    for (int k = 0; k < 128; k++){
        float yv = __shfl_sync(~0u, y[k >> 5], k & 31);
        a0 = fmaf(yv, s_w1[k * 64 + lane     ], a0);
        a1 = fmaf(yv, s_w1[k * 64 + lane + 32], a1);
    }
    a0 = fmaxf(a0, 0.f); a1 = fmaxf(a1, 0.f);
    float p0 = a0 * s_w2[lane * 3 + 0] + a1 * s_w2[(lane + 32) * 3 + 0];
    float p1 = a0 * s_w2[lane * 3 + 1] + a1 * s_w2[(lane + 32) * 3 + 1];
    float p2 = a0 * s_w2[lane * 3 + 2] + a1 * s_w2[(lane + 32) * 3 + 2];
    #pragma unroll
    for (int off = 16; off; off >>= 1){
        p0 += __shfl_xor_sync(~0u, p0, off);
        p1 += __shfl_xor_sync(~0u, p1, off);
        p2 += __shfl_xor_sync(~0u, p2, off);
    }
    if (lane == 0){
        out[node * 3 + 0] = p0 + h2b[0];
        out[node * 3 + 1] = p1 + h2b[1];
        out[node * 3 + 2] = p2 + h2b[2];
    }
}

// ---------------- host orchestration ----------------------------------------
extern "C" void kernel_launch(void* const* d_in, const int* in_sizes, int n_in,
                              void* d_out, int out_size){
    const float* x     = (const float*)d_in[0];
    const int*   eidx  = (const int*)d_in[1];
    const float* eattr = (const float*)d_in[2];
    const float* in_w  = (const float*)d_in[3];
    const float* in_b  = (const float*)d_in[4];
    const float* Wl    = (const float*)d_in[5];
    const float* bl    = (const float*)d_in[6];
    const float* Wr    = (const float*)d_in[7];
    const float* br    = (const float*)d_in[8];
    const float* We    = (const float*)d_in[9];
    const float* att   = (const float*)d_in[10];
    const float* cb    = (const float*)d_in[11];
    const float* lng   = (const float*)d_in[12];
    const float* lnb   = (const float*)d_in[13];
    const float* h1w   = (const float*)d_in[14];
    const float* h1b   = (const float*)d_in[15];
    const float* h2w   = (const float*)d_in[16];
    const float* h2b   = (const float*)d_in[17];
    float* out = (float*)d_out;

    int N  = in_sizes[0] / 128;
    int E  = in_sizes[1] / 2;
    int EP = E + N;
    int NB = (N + 1023) / 1024;

    // edge index normalization
    k_detect<<<1, 256>>>(eidx);
    k_convert<<<(E + 255) / 256, 256>>>(eidx, E);

    // CSR build (by destination)
    k_initcnt<<<(N + 255) / 256, 256>>>(N);
    k_hist<<<(E + 255) / 256, 256>>>(E);
    k_scan1<<<NB, 1024>>>(N);
    k_scan2<<<1, 32>>>(NB);
    k_scan3<<<(N + 255) / 256, 256>>>(N);
    k_copyoff<<<(N + 255) / 256, 256>>>(N);
    k_scatter<<<(EP + 255) / 256, 256>>>(E, EP);

    // self-loop attrs
    k_loopattr<<<(N * 32 + 255) / 256, 256>>>(eattr, E, N);

    // input projection -> g_h
    k_gemm128<<<(N + 15) / 16, 128>>>(x, in_w, in_b, N);

    for (int l = 0; l < 2; l++){
        const float* Wl_l  = Wl  + (size_t)l * 128 * 128;
        const float* bl_l  = bl  + (size_t)l * 128;
        const float* Wr_l  = Wr  + (size_t)l * 128 * 128;
        const float* br_l  = br  + (size_t)l * 128;
        const float* We_l  = We  + (size_t)l * 16 * 128;
        const float* att_l = att + (size_t)l * 128;
        const float* cb_l  = cb  + (size_t)l * 128;

        k_dualgemm<<<(N + 15) / 16, 128>>>(Wl_l, bl_l, Wr_l, br_l, N);
        k_edge_fused<<<(N * 32 + 255) / 256, 256>>>(eattr, We_l, att_l, cb_l, E, N);
    }

    k_final<<<(N + 7) / 8, 256>>>(lng, lnb, h1w, h1b, h2w, h2b, out, N);
}